// round 2
// baseline (speedup 1.0000x reference)
#include <cuda_runtime.h>
#include <math.h>
#include <float.h>

#define BN   64
#define LN   512
#define HN   512
#define EMBN 512
#define VN   50257
#define TSTEPS 32
#define H3   1536

// ---------------- scratch (static device globals; no allocation) ----------------
__device__ __align__(16) float g_mean[BN*HN];
__device__ __align__(16) float g_ctx[BN*HN];
__device__ __align__(16) float g_gictx[BN*H3];
__device__ __align__(16) float g_h1[BN*HN];
__device__ __align__(16) float g_h2[BN*HN];
__device__ int   g_seq[BN];
__device__ __align__(16) float g_gi[2*BN*H3];   // 2 K-split partials, i-gate GEMM
__device__ __align__(16) float g_gh[2*BN*H3];   // 2 K-split partials, h-gate GEMM

// packed fp32x2 FMA (Blackwell): d.lo = a.lo*b.lo + c.lo ; d.hi likewise
__device__ __forceinline__ void fma2(unsigned long long &c,
                                     unsigned long long a,
                                     unsigned long long b) {
    asm("fma.rn.f32x2 %0, %1, %2, %3;" : "=l"(c) : "l"(a), "l"(b), "l"(c));
}

// ---------------- one-time setup kernels ----------------
__global__ void k_init(const int* __restrict__ sos) {
    int i = blockIdx.x * blockDim.x + threadIdx.x;
    if (i < BN*HN) { g_h1[i] = 0.f; g_h2[i] = 0.f; }
    if (i < BN) g_seq[i] = sos[0];
}

// mean over valid encoder positions (uniform attention: q = 0 @ Wk.T = 0)
__global__ void k_mean(const float* __restrict__ enc, const int* __restrict__ elen) {
    int b = blockIdx.x;
    int h = blockIdx.y * 128 + threadIdx.x;
    int len = elen[b];
    const float* p = enc + (size_t)b * LN * HN + h;
    float s = 0.f;
    for (int l = 0; l < len; ++l) s += p[(size_t)l * HN];
    g_mean[b*HN + h] = s / (float)len;
}

// ctx[b,p] = sum_h mean[b,h] * Wk[p,h]
__global__ void k_ctx(const float* __restrict__ Wk) {
    __shared__ float sm[HN];
    int b = blockIdx.x, p = threadIdx.x;
    sm[p] = g_mean[b*HN + p];
    __syncthreads();
    const float4* w  = (const float4*)(Wk + (size_t)p * HN);
    const float4* s4 = (const float4*)sm;
    float acc = 0.f;
    for (int h = 0; h < HN/4; ++h) {
        float4 a = s4[h], ww = w[h];
        acc += a.x*ww.x + a.y*ww.y + a.z*ww.z + a.w*ww.w;
    }
    g_ctx[b*HN + p] = acc;
}

// gi_ctx[b,j] = bih1[j] + sum_h ctx[b,h] * Wih1[j, EMB+h]   (time-invariant)
__global__ void k_gictx(const float* __restrict__ Wih1, const float* __restrict__ bih1) {
    __shared__ float sm[HN];
    int b = blockIdx.x;
    int j = blockIdx.y * 512 + threadIdx.x;
    sm[threadIdx.x] = g_ctx[b*HN + threadIdx.x];
    __syncthreads();
    const float4* w  = (const float4*)(Wih1 + (size_t)j * (EMBN + HN) + EMBN);
    const float4* s4 = (const float4*)sm;
    float acc = bih1[j];
    for (int h = 0; h < HN/4; ++h) {
        float4 a = s4[h], ww = w[h];
        acc += a.x*ww.x + a.y*ww.y + a.z*ww.z + a.w*ww.w;
    }
    g_gictx[b*H3 + j] = acc;
}

// ---------------- per-step GRU pre-activation GEMMs ----------------
// grid: x = 24 (j-tiles of 64 over 3H), y = 2 (K-split halves), z = 2 (0: i-gemm, 1: h-gemm)
// Computes partial [64 x 64] tile of  A(64xK) @ W^T  for K-half kz.
__global__ void __launch_bounds__(256) k_gru_gemm(
    int layer,
    const float* __restrict__ emb,
    const float* __restrict__ Wi, int wsi,
    const float* __restrict__ Wh)
{
    __shared__ __align__(16) float As2[32][132];  // A duplicated: [k][2b],[2b+1]
    __shared__ __align__(16) float Bs[32][68];    // W tile: [k][n]

    const int j0 = blockIdx.x * 64;
    const int kz = blockIdx.y;
    const int zi = blockIdx.z;

    const float* W; int ws; const float* A; int gather;
    if (zi == 0) { W = Wi; ws = wsi; gather = (layer == 1); A = (layer == 1) ? emb : g_h1; }
    else         { W = Wh; ws = HN;  gather = 0;            A = (layer == 1) ? g_h1 : g_h2; }
    float* Out = (zi == 0 ? g_gi : g_gh) + kz * (BN * H3);

    const int tid = threadIdx.x;
    const int tx = tid & 15, ty = tid >> 4;

    unsigned long long acc[4][2];
#pragma unroll
    for (int i = 0; i < 4; i++) { acc[i][0] = 0ULL; acc[i][1] = 0ULL; }

    int ab[2], ak[2]; const float* arow[2];
    int bn[2], bk[2];
#pragma unroll
    for (int r = 0; r < 2; r++) {
        int idx = tid + 256*r;
        ab[r] = idx >> 3; ak[r] = (idx & 7) << 2;
        arow[r] = gather ? (emb + (size_t)g_seq[ab[r]] * EMBN) : (A + ab[r]*HN);
        bn[r] = idx >> 3; bk[r] = (idx & 7) << 2;
    }

    const int k0 = kz * 256;
    float4 pa[2], pb[2];
#pragma unroll
    for (int r = 0; r < 2; r++) pa[r] = *(const float4*)(arow[r] + k0 + ak[r]);
#pragma unroll
    for (int r = 0; r < 2; r++) pb[r] = *(const float4*)(W + (size_t)(j0+bn[r])*ws + k0 + bk[r]);

    for (int kt = 0; kt < 8; ++kt) {
        __syncthreads();
#pragma unroll
        for (int r = 0; r < 2; r++) {
            float v[4] = {pa[r].x, pa[r].y, pa[r].z, pa[r].w};
#pragma unroll
            for (int jj = 0; jj < 4; jj++) {
                As2[ak[r]+jj][2*ab[r]]   = v[jj];
                As2[ak[r]+jj][2*ab[r]+1] = v[jj];
            }
        }
#pragma unroll
        for (int r = 0; r < 2; r++) {
            float v[4] = {pb[r].x, pb[r].y, pb[r].z, pb[r].w};
#pragma unroll
            for (int jj = 0; jj < 4; jj++) Bs[bk[r]+jj][bn[r]] = v[jj];
        }
        __syncthreads();
        if (kt + 1 < 8) {
            int k1 = k0 + (kt+1)*32;
#pragma unroll
            for (int r = 0; r < 2; r++) pa[r] = *(const float4*)(arow[r] + k1 + ak[r]);
#pragma unroll
            for (int r = 0; r < 2; r++) pb[r] = *(const float4*)(W + (size_t)(j0+bn[r])*ws + k1 + bk[r]);
        }
#pragma unroll
        for (int kk = 0; kk < 32; ++kk) {
            ulonglong2 a01 = *(const ulonglong2*)&As2[kk][ty*8];
            ulonglong2 a23 = *(const ulonglong2*)&As2[kk][ty*8+4];
            ulonglong2 b01 = *(const ulonglong2*)&Bs[kk][tx*4];
            unsigned long long av[4] = {a01.x, a01.y, a23.x, a23.y};
#pragma unroll
            for (int i = 0; i < 4; i++) {
                fma2(acc[i][0], av[i], b01.x);
                fma2(acc[i][1], av[i], b01.y);
            }
        }
    }

#pragma unroll
    for (int i = 0; i < 4; i++) {
        int b = ty*4 + i;
#pragma unroll
        for (int jp = 0; jp < 2; jp++) {
            float lo = __uint_as_float((unsigned)(acc[i][jp] & 0xffffffffULL));
            float hi = __uint_as_float((unsigned)(acc[i][jp] >> 32));
            int j = j0 + tx*4 + 2*jp;
            Out[b*H3 + j]   = lo;
            Out[b*H3 + j+1] = hi;
        }
    }
}

// ---------------- GRU gate nonlinearity + state update ----------------
__global__ void k_gates(int layer,
                        const float* __restrict__ bih2,
                        const float* __restrict__ bhh)
{
    int idx = blockIdx.x * 256 + threadIdx.x;   // over B*H
    int b = idx >> 9, k = idx & 511;
    const float* gi0 = g_gi + b*H3;
    const float* gi1 = g_gi + BN*H3 + b*H3;
    const float* gh0 = g_gh + b*H3;
    const float* gh1 = g_gh + BN*H3 + b*H3;

    float bir, biz, bin;
    if (layer == 1) {
        const float* base = g_gictx + b*H3;     // includes bih1 + ctx contribution
        bir = base[k]; biz = base[k+512]; bin = base[k+1024];
    } else {
        bir = bih2[k]; biz = bih2[k+512]; bin = bih2[k+1024];
    }
    float ir  = bir + gi0[k]      + gi1[k];
    float iz  = biz + gi0[k+512]  + gi1[k+512];
    float in_ = bin + gi0[k+1024] + gi1[k+1024];
    float hr  = bhh[k]      + gh0[k]      + gh1[k];
    float hz  = bhh[k+512]  + gh0[k+512]  + gh1[k+512];
    float hn  = bhh[k+1024] + gh0[k+1024] + gh1[k+1024];

    float* h = (layer == 1) ? g_h1 : g_h2;
    float hv = h[idx];
    float r = 1.f / (1.f + expf(-(ir + hr)));
    float z = 1.f / (1.f + expf(-(iz + hz)));
    float n = tanhf(in_ + r * hn);
    h[idx] = (1.f - z) * n + z * hv;
}

// ---------------- logits GEMM: (64 x V) = h2(64x512) @ Wout^T + bout ----------------
// block tile: 64 b x 128 v, K-chunk 32, f32x2 packed FMAs, 4b x 8v per thread
__global__ void __launch_bounds__(256) k_logits(
    const float* __restrict__ Wout,
    const float* __restrict__ bout,
    float* __restrict__ out)
{
    __shared__ __align__(16) float As2[32][132];
    __shared__ __align__(16) float Bs[32][132];

    const int v0 = blockIdx.x * 128;
    const int tid = threadIdx.x;
    const int tx = tid & 15, ty = tid >> 4;

    unsigned long long acc[4][4];
#pragma unroll
    for (int i = 0; i < 4; i++)
#pragma unroll
        for (int j = 0; j < 4; j++) acc[i][j] = 0ULL;

    float4 pa[2], pb[4];
#pragma unroll
    for (int r = 0; r < 2; r++) {
        int idx = tid + 256*r;
        int b = idx >> 3, kk4 = (idx & 7) << 2;
        pa[r] = *(const float4*)(g_h2 + b*HN + kk4);
    }
#pragma unroll
    for (int r = 0; r < 4; r++) {
        int idx = tid + 256*r;
        int vv = idx >> 3, kk4 = (idx & 7) << 2;
        int v = v0 + vv;
        pb[r] = (v < VN) ? *(const float4*)(Wout + (size_t)v*HN + kk4)
                         : make_float4(0.f,0.f,0.f,0.f);
    }

    for (int kt = 0; kt < 16; ++kt) {
        __syncthreads();
#pragma unroll
        for (int r = 0; r < 2; r++) {
            int idx = tid + 256*r;
            int b = idx >> 3, kk4 = (idx & 7) << 2;
            float v4[4] = {pa[r].x, pa[r].y, pa[r].z, pa[r].w};
#pragma unroll
            for (int jj = 0; jj < 4; jj++) {
                As2[kk4+jj][2*b]   = v4[jj];
                As2[kk4+jj][2*b+1] = v4[jj];
            }
        }
#pragma unroll
        for (int r = 0; r < 4; r++) {
            int idx = tid + 256*r;
            int vv = idx >> 3, kk4 = (idx & 7) << 2;
            float v4[4] = {pb[r].x, pb[r].y, pb[r].z, pb[r].w};
#pragma unroll
            for (int jj = 0; jj < 4; jj++) Bs[kk4+jj][vv] = v4[jj];
        }
        __syncthreads();
        if (kt + 1 < 16) {
            int k1 = (kt+1)*32;
#pragma unroll
            for (int r = 0; r < 2; r++) {
                int idx = tid + 256*r;
                int b = idx >> 3, kk4 = (idx & 7) << 2;
                pa[r] = *(const float4*)(g_h2 + b*HN + k1 + kk4);
            }
#pragma unroll
            for (int r = 0; r < 4; r++) {
                int idx = tid + 256*r;
                int vv = idx >> 3, kk4 = (idx & 7) << 2;
                int v = v0 + vv;
                pb[r] = (v < VN) ? *(const float4*)(Wout + (size_t)v*HN + k1 + kk4)
                                 : make_float4(0.f,0.f,0.f,0.f);
            }
        }
#pragma unroll
        for (int kk = 0; kk < 32; ++kk) {
            ulonglong2 a01 = *(const ulonglong2*)&As2[kk][ty*8];
            ulonglong2 a23 = *(const ulonglong2*)&As2[kk][ty*8+4];
            ulonglong2 b01 = *(const ulonglong2*)&Bs[kk][tx*8];
            ulonglong2 b23 = *(const ulonglong2*)&Bs[kk][tx*8+4];
            unsigned long long av[4] = {a01.x, a01.y, a23.x, a23.y};
            unsigned long long bv[4] = {b01.x, b01.y, b23.x, b23.y};
#pragma unroll
            for (int i = 0; i < 4; i++)
#pragma unroll
                for (int j = 0; j < 4; j++) fma2(acc[i][j], av[i], bv[j]);
        }
    }

#pragma unroll
    for (int i = 0; i < 4; i++) {
        int b = ty*4 + i;
#pragma unroll
        for (int jp = 0; jp < 4; jp++) {
            int v = v0 + tx*8 + 2*jp;
            float lo = __uint_as_float((unsigned)(acc[i][jp] & 0xffffffffULL));
            float hi = __uint_as_float((unsigned)(acc[i][jp] >> 32));
            if (v     < VN) out[(size_t)b*VN + v]     = lo + bout[v];
            if (v + 1 < VN) out[(size_t)b*VN + v + 1] = hi + bout[v+1];
        }
    }
}

// ---------------- greedy argmax (first-max tie-break, matches jnp.argmax) ----------------
__global__ void k_argmax(const float* __restrict__ logits_t) {
    int b = blockIdx.x;
    int tid = threadIdx.x;
    const float* row = logits_t + (size_t)b * VN;
    float bv = -FLT_MAX; int bi = 0;
    for (int v = tid; v < VN; v += 256) {
        float x = row[v];
        if (x > bv) { bv = x; bi = v; }
    }
    __shared__ float sv[256];
    __shared__ int   si[256];
    sv[tid] = bv; si[tid] = bi;
    __syncthreads();
    for (int s = 128; s > 0; s >>= 1) {
        if (tid < s) {
            if (sv[tid+s] > sv[tid] || (sv[tid+s] == sv[tid] && si[tid+s] < si[tid])) {
                sv[tid] = sv[tid+s]; si[tid] = si[tid+s];
            }
        }
        __syncthreads();
    }
    if (tid == 0) g_seq[b] = si[0];
}

// ---------------- launch ----------------
extern "C" void kernel_launch(void* const* d_in, const int* in_sizes, int n_in,
                              void* d_out, int out_size) {
    const float* encoded = (const float*)d_in[0];
    const int*   elen    = (const int*)  d_in[1];
    const int*   sos     = (const int*)  d_in[2];
    // d_in[3] generated_seqlen == 32 (fixed by setup)
    const float* emb     = (const float*)d_in[4];
    const float* Wk      = (const float*)d_in[5];
    const float* Wih1    = (const float*)d_in[6];
    const float* Whh1    = (const float*)d_in[7];
    const float* bih1    = (const float*)d_in[8];
    const float* bhh1    = (const float*)d_in[9];
    const float* Wih2    = (const float*)d_in[10];
    const float* Whh2    = (const float*)d_in[11];
    const float* bih2    = (const float*)d_in[12];
    const float* bhh2    = (const float*)d_in[13];
    const float* Wout    = (const float*)d_in[14];
    const float* bout    = (const float*)d_in[15];
    float* out = (float*)d_out;

    k_init<<<(BN*HN + 255)/256, 256>>>(sos);
    k_mean<<<dim3(BN, HN/128), 128>>>(encoded, elen);
    k_ctx<<<BN, HN>>>(Wk);
    k_gictx<<<dim3(BN, 3), 512>>>(Wih1, bih1);

    const int vblocks = (VN + 127) / 128;
    for (int t = 0; t < TSTEPS; ++t) {
        k_gru_gemm<<<dim3(24, 2, 2), 256>>>(1, emb, Wih1, EMBN + HN, Whh1);
        k_gates<<<(BN*HN)/256, 256>>>(1, nullptr, bhh1);
        k_gru_gemm<<<dim3(24, 2, 2), 256>>>(2, emb, Wih2, HN, Whh2);
        k_gates<<<(BN*HN)/256, 256>>>(2, bih2, bhh2);
        float* out_t = out + (size_t)t * BN * VN;
        k_logits<<<vblocks, 256>>>(Wout, bout, out_t);
        if (t + 1 < TSTEPS) k_argmax<<<BN, 256>>>(out_t);
    }
}

// round 4
// speedup vs baseline: 1.5032x; 1.5032x over previous
#include <cuda_runtime.h>
#include <math.h>
#include <float.h>

#define BN   64
#define LN   512
#define HN   512
#define EMBN 512
#define VN   50257
#define TSTEPS 32
#define H3   1536

#define VTILE 96
#define NTILES ((VN + VTILE - 1) / VTILE)   // 524

// ---------------- scratch (static device globals; no allocation) ----------------
__device__ __align__(16) float g_gictx[BN*H3];
__device__ __align__(16) float g_h1[BN*HN];
__device__ __align__(16) float g_h2[BN*HN];
__device__ int   g_seq[BN];
__device__ __align__(16) float g_gi[2*BN*H3];   // 2 K-split partials, i-gate GEMM
__device__ __align__(16) float g_gh[2*BN*H3];   // 2 K-split partials, h-gate GEMM
__device__ float g_pval[NTILES*BN];             // per-tile argmax partials
__device__ int   g_pidx[NTILES*BN];

// packed fp32x2 FMA (Blackwell)
__device__ __forceinline__ void fma2(unsigned long long &c,
                                     unsigned long long a,
                                     unsigned long long b) {
    asm("fma.rn.f32x2 %0, %1, %2, %3;" : "=l"(c) : "l"(a), "l"(b), "l"(c));
}

// ---------------- fused one-time setup ----------------
// Per-b chain: mean over valid positions (uniform attn, q=0) -> ctx = Wk @ mean
// -> gictx = bih1 + Wih1[:,EMB:] @ ctx. Also zero h1/h2, seed g_seq.
__global__ void __launch_bounds__(256) k_setup(
    const float* __restrict__ enc, const int* __restrict__ elen,
    const int* __restrict__ sos,
    const float* __restrict__ Wk,
    const float* __restrict__ Wih1, const float* __restrict__ bih1)
{
    __shared__ float s_mean[HN];
    __shared__ float s_ctx[HN];
    int b = blockIdx.x, t = threadIdx.x;
    int len = elen[b];
    float inv = 1.f / (float)len;

    // mean
    for (int h = t; h < HN; h += 256) {
        const float* p = enc + (size_t)b * LN * HN + h;
        float s = 0.f;
        for (int l = 0; l < len; ++l) s += p[(size_t)l * HN];
        s_mean[h] = s * inv;
    }
    // zero states, seed seq
    g_h1[b*HN + t] = 0.f; g_h1[b*HN + t + 256] = 0.f;
    g_h2[b*HN + t] = 0.f; g_h2[b*HN + t + 256] = 0.f;
    if (t == 0) g_seq[b] = sos[0];
    __syncthreads();

    // ctx[p] = dot(mean, Wk[p,:])
    const float4* m4 = (const float4*)s_mean;
    for (int p = t; p < HN; p += 256) {
        const float4* w = (const float4*)(Wk + (size_t)p * HN);
        float acc = 0.f;
        for (int h = 0; h < HN/4; ++h) {
            float4 a = m4[h], ww = w[h];
            acc += a.x*ww.x + a.y*ww.y + a.z*ww.z + a.w*ww.w;
        }
        s_ctx[p] = acc;
    }
    __syncthreads();

    // gictx[j] = bih1[j] + dot(ctx, Wih1[j, EMB:])
    const float4* c4 = (const float4*)s_ctx;
    for (int j = t; j < H3; j += 256) {
        const float4* w = (const float4*)(Wih1 + (size_t)j * (EMBN + HN) + EMBN);
        float acc = bih1[j];
        for (int h = 0; h < HN/4; ++h) {
            float4 a = c4[h], ww = w[h];
            acc += a.x*ww.x + a.y*ww.y + a.z*ww.z + a.w*ww.w;
        }
        g_gictx[b*H3 + j] = acc;
    }
}

// ---------------- per-step GRU pre-activation GEMMs ----------------
__global__ void __launch_bounds__(256) k_gru_gemm(
    int layer,
    const float* __restrict__ emb,
    const float* __restrict__ Wi, int wsi,
    const float* __restrict__ Wh)
{
    __shared__ __align__(16) float As2[32][132];  // A duplicated: [k][2b],[2b+1]
    __shared__ __align__(16) float Bs[32][68];    // W tile: [k][n]

    const int j0 = blockIdx.x * 64;
    const int kz = blockIdx.y;
    const int zi = blockIdx.z;

    const float* W; int ws; const float* A; int gather;
    if (zi == 0) { W = Wi; ws = wsi; gather = (layer == 1); A = (layer == 1) ? emb : g_h1; }
    else         { W = Wh; ws = HN;  gather = 0;            A = (layer == 1) ? g_h1 : g_h2; }
    float* Out = (zi == 0 ? g_gi : g_gh) + kz * (BN * H3);

    const int tid = threadIdx.x;
    const int tx = tid & 15, ty = tid >> 4;

    unsigned long long acc[4][2];
#pragma unroll
    for (int i = 0; i < 4; i++) { acc[i][0] = 0ULL; acc[i][1] = 0ULL; }

    int ab[2], ak[2]; const float* arow[2];
    int bn[2], bk[2];
#pragma unroll
    for (int r = 0; r < 2; r++) {
        int idx = tid + 256*r;
        ab[r] = idx >> 3; ak[r] = (idx & 7) << 2;
        arow[r] = gather ? (emb + (size_t)g_seq[ab[r]] * EMBN) : (A + ab[r]*HN);
        bn[r] = idx >> 3; bk[r] = (idx & 7) << 2;
    }

    const int k0 = kz * 256;
    float4 pa[2], pb[2];
#pragma unroll
    for (int r = 0; r < 2; r++) pa[r] = *(const float4*)(arow[r] + k0 + ak[r]);
#pragma unroll
    for (int r = 0; r < 2; r++) pb[r] = *(const float4*)(W + (size_t)(j0+bn[r])*ws + k0 + bk[r]);

    for (int kt = 0; kt < 8; ++kt) {
        __syncthreads();
#pragma unroll
        for (int r = 0; r < 2; r++) {
            float v[4] = {pa[r].x, pa[r].y, pa[r].z, pa[r].w};
#pragma unroll
            for (int jj = 0; jj < 4; jj++) {
                As2[ak[r]+jj][2*ab[r]]   = v[jj];
                As2[ak[r]+jj][2*ab[r]+1] = v[jj];
            }
        }
#pragma unroll
        for (int r = 0; r < 2; r++) {
            float v[4] = {pb[r].x, pb[r].y, pb[r].z, pb[r].w};
#pragma unroll
            for (int jj = 0; jj < 4; jj++) Bs[bk[r]+jj][bn[r]] = v[jj];
        }
        __syncthreads();
        if (kt + 1 < 8) {
            int k1 = k0 + (kt+1)*32;
#pragma unroll
            for (int r = 0; r < 2; r++) pa[r] = *(const float4*)(arow[r] + k1 + ak[r]);
#pragma unroll
            for (int r = 0; r < 2; r++) pb[r] = *(const float4*)(W + (size_t)(j0+bn[r])*ws + k1 + bk[r]);
        }
#pragma unroll
        for (int kk = 0; kk < 32; ++kk) {
            ulonglong2 a01 = *(const ulonglong2*)&As2[kk][ty*8];
            ulonglong2 a23 = *(const ulonglong2*)&As2[kk][ty*8+4];
            ulonglong2 b01 = *(const ulonglong2*)&Bs[kk][tx*4];
            unsigned long long av[4] = {a01.x, a01.y, a23.x, a23.y};
#pragma unroll
            for (int i = 0; i < 4; i++) {
                fma2(acc[i][0], av[i], b01.x);
                fma2(acc[i][1], av[i], b01.y);
            }
        }
    }

#pragma unroll
    for (int i = 0; i < 4; i++) {
        int b = ty*4 + i;
#pragma unroll
        for (int jp = 0; jp < 2; jp++) {
            float lo = __uint_as_float((unsigned)(acc[i][jp] & 0xffffffffULL));
            float hi = __uint_as_float((unsigned)(acc[i][jp] >> 32));
            int j = j0 + tx*4 + 2*jp;
            Out[b*H3 + j]   = lo;
            Out[b*H3 + j+1] = hi;
        }
    }
}

// ---------------- GRU gate nonlinearity + state update ----------------
__global__ void k_gates(int layer,
                        const float* __restrict__ bih2,
                        const float* __restrict__ bhh)
{
    int idx = blockIdx.x * 256 + threadIdx.x;   // over B*H
    int b = idx >> 9, k = idx & 511;
    const float* gi0 = g_gi + b*H3;
    const float* gi1 = g_gi + BN*H3 + b*H3;
    const float* gh0 = g_gh + b*H3;
    const float* gh1 = g_gh + BN*H3 + b*H3;

    float bir, biz, bin;
    if (layer == 1) {
        const float* base = g_gictx + b*H3;     // includes bih1 + ctx contribution
        bir = base[k]; biz = base[k+512]; bin = base[k+1024];
    } else {
        bir = bih2[k]; biz = bih2[k+512]; bin = bih2[k+1024];
    }
    float ir  = bir + gi0[k]      + gi1[k];
    float iz  = biz + gi0[k+512]  + gi1[k+512];
    float in_ = bin + gi0[k+1024] + gi1[k+1024];
    float hr  = bhh[k]      + gh0[k]      + gh1[k];
    float hz  = bhh[k+512]  + gh0[k+512]  + gh1[k+512];
    float hn  = bhh[k+1024] + gh0[k+1024] + gh1[k+1024];

    float* h = (layer == 1) ? g_h1 : g_h2;
    float hv = h[idx];
    float r = 1.f / (1.f + expf(-(ir + hr)));
    float z = 1.f / (1.f + expf(-(iz + hz)));
    float n = tanhf(in_ + r * hn);
    h[idx] = (1.f - z) * n + z * hv;
}

// ---------------- logits GEMM + fused partial argmax ----------------
// tile: 64 b x 96 v (524 tiles -> ~13% ceil-waste vs 50% at 128v),
// K-chunk 32, f32x2 packed FMAs, per-thread 4b x 6v.
__global__ void __launch_bounds__(256) k_logits(
    const float* __restrict__ Wout,
    const float* __restrict__ bout,
    float* __restrict__ out)
{
    __shared__ __align__(16) float As2[32][132];
    __shared__ __align__(16) float Bs[32][100];
    __shared__ float rv[64][17];
    __shared__ int   ri[64][17];

    const int v0 = blockIdx.x * VTILE;
    const int tid = threadIdx.x;
    const int tx = tid & 15, ty = tid >> 4;

    unsigned long long acc[4][3];
#pragma unroll
    for (int i = 0; i < 4; i++)
#pragma unroll
        for (int j = 0; j < 3; j++) acc[i][j] = 0ULL;

    float4 pa[2], pb[3];
#pragma unroll
    for (int r = 0; r < 2; r++) {
        int idx = tid + 256*r;
        int b = idx >> 3, kk4 = (idx & 7) << 2;
        pa[r] = *(const float4*)(g_h2 + b*HN + kk4);
    }
#pragma unroll
    for (int r = 0; r < 3; r++) {
        int idx = tid + 256*r;
        int vv = idx >> 3, kk4 = (idx & 7) << 2;
        int v = v0 + vv;
        pb[r] = (v < VN) ? *(const float4*)(Wout + (size_t)v*HN + kk4)
                         : make_float4(0.f,0.f,0.f,0.f);
    }

    for (int kt = 0; kt < 16; ++kt) {
        __syncthreads();
#pragma unroll
        for (int r = 0; r < 2; r++) {
            int idx = tid + 256*r;
            int b = idx >> 3, kk4 = (idx & 7) << 2;
            float v4[4] = {pa[r].x, pa[r].y, pa[r].z, pa[r].w};
#pragma unroll
            for (int jj = 0; jj < 4; jj++) {
                As2[kk4+jj][2*b]   = v4[jj];
                As2[kk4+jj][2*b+1] = v4[jj];
            }
        }
#pragma unroll
        for (int r = 0; r < 3; r++) {
            int idx = tid + 256*r;
            int vv = idx >> 3, kk4 = (idx & 7) << 2;
            float v4[4] = {pb[r].x, pb[r].y, pb[r].z, pb[r].w};
#pragma unroll
            for (int jj = 0; jj < 4; jj++) Bs[kk4+jj][vv] = v4[jj];
        }
        __syncthreads();
        if (kt + 1 < 16) {
            int k1 = (kt+1)*32;
#pragma unroll
            for (int r = 0; r < 2; r++) {
                int idx = tid + 256*r;
                int b = idx >> 3, kk4 = (idx & 7) << 2;
                pa[r] = *(const float4*)(g_h2 + b*HN + k1 + kk4);
            }
#pragma unroll
            for (int r = 0; r < 3; r++) {
                int idx = tid + 256*r;
                int vv = idx >> 3, kk4 = (idx & 7) << 2;
                int v = v0 + vv;
                pb[r] = (v < VN) ? *(const float4*)(Wout + (size_t)v*HN + k1 + kk4)
                                 : make_float4(0.f,0.f,0.f,0.f);
            }
        }
#pragma unroll
        for (int kk = 0; kk < 32; ++kk) {
            ulonglong2 a01 = *(const ulonglong2*)&As2[kk][ty*8];
            ulonglong2 a23 = *(const ulonglong2*)&As2[kk][ty*8+4];
            // per-thread v span = 24B: three 8-byte (aligned) pair loads
            const unsigned long long* bp = (const unsigned long long*)&Bs[kk][tx*6];
            unsigned long long bv0 = bp[0], bv1 = bp[1], bv2 = bp[2];
            unsigned long long av[4] = {a01.x, a01.y, a23.x, a23.y};
#pragma unroll
            for (int i = 0; i < 4; i++) {
                fma2(acc[i][0], av[i], bv0);
                fma2(acc[i][1], av[i], bv1);
                fma2(acc[i][2], av[i], bv2);
            }
        }
    }

    // bias pairs for this thread's 6 columns
    float blo[3], bhi[3];
#pragma unroll
    for (int jp = 0; jp < 3; jp++) {
        int v = v0 + tx*6 + 2*jp;
        blo[jp] = (v     < VN) ? bout[v]   : 0.f;
        bhi[jp] = (v + 1 < VN) ? bout[v+1] : 0.f;
    }

    __syncthreads();  // done with As2/Bs before rv/ri use (separate arrays, but order writes)

#pragma unroll
    for (int i = 0; i < 4; i++) {
        int b = ty*4 + i;
        float mval = -FLT_MAX; int midx = 0x7fffffff;
#pragma unroll
        for (int jp = 0; jp < 3; jp++) {
            int v = v0 + tx*6 + 2*jp;
            float lo = __uint_as_float((unsigned)(acc[i][jp] & 0xffffffffULL)) + blo[jp];
            float hi = __uint_as_float((unsigned)(acc[i][jp] >> 32)) + bhi[jp];
            if (v < VN) {
                out[(size_t)b*VN + v] = lo;
                if (lo > mval) { mval = lo; midx = v; }
            }
            if (v + 1 < VN) {
                out[(size_t)b*VN + v + 1] = hi;
                if (hi > mval) { mval = hi; midx = v + 1; }
            }
        }
        rv[b][tx] = mval; ri[b][tx] = midx;
    }
    __syncthreads();

    // one thread per b-row reduces 16 partials
    if (tid < 64) {
        int b = tid;
        float mval = rv[b][0]; int midx = ri[b][0];
#pragma unroll
        for (int j = 1; j < 16; j++) {
            float v = rv[b][j]; int ix = ri[b][j];
            if (v > mval || (v == mval && ix < midx)) { mval = v; midx = ix; }
        }
        g_pval[(size_t)blockIdx.x*BN + b] = mval;
        g_pidx[(size_t)blockIdx.x*BN + b] = midx;
    }
}

// ---------------- final argmax reduce over tiles ----------------
__global__ void k_amax_final() {
    int b = blockIdx.x, t = threadIdx.x;
    float mval = -FLT_MAX; int midx = 0x7fffffff;
    for (int s = t; s < NTILES; s += 256) {
        float v = g_pval[(size_t)s*BN + b]; int ix = g_pidx[(size_t)s*BN + b];
        if (v > mval || (v == mval && ix < midx)) { mval = v; midx = ix; }
    }
    __shared__ float sv[256];
    __shared__ int   si[256];
    sv[t] = mval; si[t] = midx;
    __syncthreads();
    for (int s = 128; s > 0; s >>= 1) {
        if (t < s) {
            if (sv[t+s] > sv[t] || (sv[t+s] == sv[t] && si[t+s] < si[t])) {
                sv[t] = sv[t+s]; si[t] = si[t+s];
            }
        }
        __syncthreads();
    }
    if (t == 0) g_seq[b] = si[0];
}

// ---------------- launch ----------------
extern "C" void kernel_launch(void* const* d_in, const int* in_sizes, int n_in,
                              void* d_out, int out_size) {
    const float* encoded = (const float*)d_in[0];
    const int*   elen    = (const int*)  d_in[1];
    const int*   sos     = (const int*)  d_in[2];
    const float* emb     = (const float*)d_in[4];
    const float* Wk      = (const float*)d_in[5];
    const float* Wih1    = (const float*)d_in[6];
    const float* Whh1    = (const float*)d_in[7];
    // bih1 folded into setup (d_in[8]); bhh1 = d_in[9]
    const float* bih1    = (const float*)d_in[8];
    const float* bhh1    = (const float*)d_in[9];
    const float* Wih2    = (const float*)d_in[10];
    const float* Whh2    = (const float*)d_in[11];
    const float* bih2    = (const float*)d_in[12];
    const float* bhh2    = (const float*)d_in[13];
    const float* Wout    = (const float*)d_in[14];
    const float* bout    = (const float*)d_in[15];
    float* out = (float*)d_out;

    // launch 0: fused setup  (so per-step k_logits lands at capture index 5)
    k_setup<<<BN, 256>>>(encoded, elen, sos, Wk, Wih1, bih1);

    for (int t = 0; t < TSTEPS; ++t) {
        k_gru_gemm<<<dim3(24, 2, 2), 256>>>(1, emb, Wih1, EMBN + HN, Whh1);
        k_gates<<<(BN*HN)/256, 256>>>(1, nullptr, bhh1);
        k_gru_gemm<<<dim3(24, 2, 2), 256>>>(2, emb, Wih2, HN, Whh2);
        k_gates<<<(BN*HN)/256, 256>>>(2, bih2, bhh2);
        float* out_t = out + (size_t)t * BN * VN;
        k_logits<<<NTILES, 256>>>(Wout, bout, out_t);
        if (t + 1 < TSTEPS) k_amax_final<<<BN, 256>>>();
    }
}